// round 10
// baseline (speedup 1.0000x reference)
#include <cuda_runtime.h>
#include <cstdint>

// SubjectLayer: 256 SGEMMs (M=256,K=256,N=3000), tf32 mma.sync m16n8k8.
// R10: A fragments LDG.128 direct from fragment-ordered gmem scratch (L2-hot),
// ring-4 register prefetch 2 kk-steps ahead (crosses barriers freely).
// B tile in smem, R8 layout (row-major [k][n], coalesced cp.async, conflict-free
// LDS.32 fragments), half-granularity double buffering. Raw-f32 B (tf32 trunc).

#define NSP 3000
#define CIN 256
#define NSUBJ 128
#define TM 128
#define TN 128
#define TK 32
#define NCHUNK 8

#define BS_STRIDE 136
#define B_WORDS (TK * BS_STRIDE)       // 4352
#define SMEM_BYTES (2 * B_WORDS * 4)   // 34816

// Fragment-ordered weights: [s][c(8)][mt(16)][kk(4)][lane(32)][r(4)]
__device__ uint32_t g_wfrag[NSUBJ * CIN * CIN];

__device__ __forceinline__ uint32_t f2tf32(float f) {
    uint32_t r;
    asm("cvt.rna.tf32.f32 %0, %1;" : "=r"(r) : "f"(f));
    return r;
}
__device__ __forceinline__ void cp16z(uint32_t dst, const void* src, int src_size) {
    asm volatile("cp.async.cg.shared.global [%0], [%1], 16, %2;\n"
                 :: "r"(dst), "l"(src), "r"(src_size));
}
__device__ __forceinline__ void mma_tf32(float* d, const uint4 a,
                                         uint32_t b0, uint32_t b1) {
    asm volatile(
        "mma.sync.aligned.m16n8k8.row.col.f32.tf32.tf32.f32 "
        "{%0,%1,%2,%3}, {%4,%5,%6,%7}, {%8,%9}, {%0,%1,%2,%3};\n"
        : "+f"(d[0]), "+f"(d[1]), "+f"(d[2]), "+f"(d[3])
        : "r"(a.x), "r"(a.y), "r"(a.z), "r"(a.w), "r"(b0), "r"(b1));
}

// ---- Prologue: weights f32 -> tf32 fragment order (unchanged, proven) ----
__global__ __launch_bounds__(256)
void wfrag_kernel(const float* __restrict__ w) {
    const int idx  = blockIdx.x * 256 + threadIdx.x;
    const int lane = idx & 31;
    const int kk   = (idx >> 5) & 3;
    const int mt   = (idx >> 7) & 15;
    const int c    = (idx >> 11) & 7;
    const int s    = idx >> 14;
    const int g = lane >> 2, t = lane & 3;
    const int m = mt * 16 + g;
    const int k = c * 32 + kk * 8 + t;
    const float* ws = w + (size_t)s * CIN * CIN;
    uint4 r;
    r.x = f2tf32(ws[(size_t)m       * CIN + k]);
    r.y = f2tf32(ws[(size_t)(m + 8) * CIN + k]);
    r.z = f2tf32(ws[(size_t)m       * CIN + k + 4]);
    r.w = f2tf32(ws[(size_t)(m + 8) * CIN + k + 4]);
    *reinterpret_cast<uint4*>(g_wfrag + (size_t)idx * 4) = r;
}

// ---- Main GEMM ----
extern __shared__ uint32_t smem[];

__global__ __launch_bounds__(256, 2)
void subject_tf32_kernel(const float* __restrict__ x,
                         const float* __restrict__ bias,
                         const int* __restrict__ subj,
                         float* __restrict__ out)
{
    const int b  = blockIdx.z;
    const int m0 = blockIdx.y * TM;
    const int n0 = blockIdx.x * TN;

    const int s = subj[b];
    const float* __restrict__ X  = x    + (size_t)b * CIN * NSP;
    const float* __restrict__ Bv = bias + (size_t)s * CIN;
    float* __restrict__ O        = out  + (size_t)b * CIN * NSP;

    const int tid    = threadIdx.x;
    const int wid    = tid >> 5;
    const int lane   = tid & 31;
    const int warp_m = wid & 3;
    const int warp_n = wid >> 2;
    const int group  = lane >> 2;
    const int tig    = lane & 3;
    const int bn     = warp_n * 64;

    // A word address: (((s*8+c)*16 + m16 + mtl + half)*4 + kk)*128 + lane*4
    //              = s*65536 + c*8192 + (m16+mtl+half)*512 + kk*128 + lane*4
    const int m16 = m0 >> 4;
    const int mtl = warp_m * 2;
    const uint32_t* __restrict__ Wbase =
        g_wfrag + (size_t)s * 65536 + (size_t)(m16 + mtl) * 512 + lane * 4;

    uint32_t* Bs = smem;
    const uint32_t bs_u32 = (uint32_t)__cvta_generic_to_shared(Bs);

    float acc[2][8][4];
    #pragma unroll
    for (int mi = 0; mi < 2; mi++)
        #pragma unroll
        for (int ni = 0; ni < 8; ni++)
            #pragma unroll
            for (int r = 0; r < 4; r++)
                acc[mi][ni][r] = 0.0f;

    // B cp.async coords (R8)
    const int b_k  = tid >> 5;
    const int b_n4 = (tid & 31) << 2;
    const int gb_n = n0 + b_n4;
    const int b_ok = (gb_n < NSP);

    auto load_Bchunk = [&](int buf, int c) {
        const int k0 = c * TK;
        uint32_t bbase = bs_u32 + (uint32_t)buf * B_WORDS * 4;
        #pragma unroll
        for (int j = 0; j < 4; j++) {
            int k = b_k + j * 8;
            cp16z(bbase + (uint32_t)(k * BS_STRIDE + b_n4) * 4,
                  X + (size_t)(k0 + k) * NSP + (b_ok ? gb_n : 0),
                  b_ok ? 16 : 0);
        }
        asm volatile("cp.async.commit_group;\n");
    };

    // A ring: slot = kk of target (g & 3 since g = c*4+kk).
    uint4 a[4][2];
    auto ldgA = [&](int slot, int c, int kk) {
        const uint32_t* p = Wbase + (size_t)c * 8192 + kk * 128;
        a[slot][0] = *reinterpret_cast<const uint4*>(p);
        a[slot][1] = *reinterpret_cast<const uint4*>(p + 512);
    };

    // B fragments: half-granularity double buffer. half = ni group of 4.
    uint32_t bw[2][8];
    auto load_bhalf = [&](uint32_t* d, const uint32_t* B, int kk, int half) {
        const int r0 = (kk * 8 + tig) * BS_STRIDE + bn + half * 32 + group;
        #pragma unroll
        for (int j = 0; j < 4; j++) {
            d[2 * j]     = B[r0 + j * 8];
            d[2 * j + 1] = B[r0 + 4 * BS_STRIDE + j * 8];
        }
    };

    // Prologue.
    load_Bchunk(0, 0);
    ldgA(0, 0, 0);
    ldgA(1, 0, 1);
    asm volatile("cp.async.wait_group 0;\n");
    __syncthreads();
    load_bhalf(bw[0], Bs, 0, 0);

    #pragma unroll 1
    for (int c = 0; c < NCHUNK; c++) {
        const int buf = c & 1;
        const uint32_t* B  = Bs + buf * B_WORDS;
        const uint32_t* Bn = Bs + (buf ^ 1) * B_WORDS;
        if (c + 1 < NCHUNK) load_Bchunk(buf ^ 1, c + 1);

        #pragma unroll
        for (int kk = 0; kk < 4; kk++) {
            // Prefetch A for g+2 (slot (kk+2)&3); crosses barriers freely.
            if (kk < 2) {
                ldgA(kk + 2, c, kk + 2);
            } else if (c + 1 < NCHUNK) {
                ldgA(kk - 2, c + 1, kk - 2);
            }
            #pragma unroll
            for (int h = 0; h < 2; h++) {
                const int sidx = kk * 2 + h;
                if (sidx < 7)
                    load_bhalf(bw[(sidx + 1) & 1], B, (sidx + 1) >> 1, (sidx + 1) & 1);
                const uint32_t* cur = bw[sidx & 1];
                #pragma unroll
                for (int j = 0; j < 4; j++) {
                    const int ni = h * 4 + j;
                    mma_tf32(acc[0][ni], a[kk][0], cur[2 * j], cur[2 * j + 1]);
                    mma_tf32(acc[1][ni], a[kk][1], cur[2 * j], cur[2 * j + 1]);
                }
            }
        }

        if (c + 1 < NCHUNK) {
            asm volatile("cp.async.wait_group 0;\n");
            __syncthreads();
            load_bhalf(bw[0], Bn, 0, 0);
        }
    }

    // Epilogue: bias add + float2 stores.
    const int am = warp_m * 32;
    #pragma unroll
    for (int mi = 0; mi < 2; mi++) {
        const int mrow = m0 + am + mi * 16 + group;
        const float bv0 = Bv[mrow];
        const float bv1 = Bv[mrow + 8];
        #pragma unroll
        for (int ni = 0; ni < 8; ni++) {
            const int n = n0 + bn + ni * 8 + tig * 2;
            if (n < NSP) {
                float2 v0 = make_float2(acc[mi][ni][0] + bv0, acc[mi][ni][1] + bv0);
                *reinterpret_cast<float2*>(&O[(size_t)mrow * NSP + n]) = v0;
                float2 v1 = make_float2(acc[mi][ni][2] + bv1, acc[mi][ni][3] + bv1);
                *reinterpret_cast<float2*>(&O[(size_t)(mrow + 8) * NSP + n]) = v1;
            }
        }
    }
}

extern "C" void kernel_launch(void* const* d_in, const int* in_sizes, int n_in,
                              void* d_out, int out_size) {
    const float* x      = (const float*)d_in[0];
    const float* weight = (const float*)d_in[1];
    const float* bias   = (const float*)d_in[2];
    const int*   subj   = (const int*)d_in[3];
    float*       out    = (float*)d_out;

    // 1) weights -> tf32 fragment-ordered scratch
    wfrag_kernel<<<NSUBJ * CIN * CIN / 4 / 256, 256>>>(weight);

    // 2) main GEMM
    cudaFuncSetAttribute(subject_tf32_kernel,
                         cudaFuncAttributeMaxDynamicSharedMemorySize, SMEM_BYTES);
    dim3 block(256);
    dim3 grid((NSP + TN - 1) / TN, CIN / TM, 256);   // (24, 2, 256)
    subject_tf32_kernel<<<grid, block, SMEM_BYTES>>>(x, bias, subj, out);
}

// round 11
// speedup vs baseline: 1.4691x; 1.4691x over previous
#include <cuda_runtime.h>
#include <cstdint>

// SubjectLayer: 256 SGEMMs (M=256,K=256,N=3000), tf32 mma.sync m16n8k8.
// R11 = R8 (best: 569us) + 3-stage smem ring so the per-chunk cp.async wait
// covers a full chunk of compute (wait_group 1 instead of 0).
// A: fragment-ordered tf32 scratch, LDS.128 frags. B: raw-f32 (tf32 HW trunc),
// row-major [k][n] smem, conflict-free LDS.32 frags, double-buffered across kk.

#define NSP 3000
#define CIN 256
#define NSUBJ 128
#define TM 128
#define TN 128
#define TK 32
#define NCHUNK 8
#define NSTAGE 3

#define A_WORDS 4096                    // 128x32 tf32 fragment-ordered per stage
#define BS_STRIDE 136
#define B_WORDS (TK * BS_STRIDE)        // 4352
#define STAGE_WORDS (A_WORDS + B_WORDS) // 8448
#define SMEM_BYTES (NSTAGE * STAGE_WORDS * 4)   // 101376

// Fragment-ordered weights: [s][c(8)][mt(16)][kk(4)][lane(32)][r(4)]
__device__ uint32_t g_wfrag[NSUBJ * CIN * CIN];

__device__ __forceinline__ uint32_t f2tf32(float f) {
    uint32_t r;
    asm("cvt.rna.tf32.f32 %0, %1;" : "=r"(r) : "f"(f));
    return r;
}
__device__ __forceinline__ void cp16(uint32_t dst, const void* src) {
    asm volatile("cp.async.cg.shared.global [%0], [%1], 16;\n" :: "r"(dst), "l"(src));
}
__device__ __forceinline__ void cp16z(uint32_t dst, const void* src, int src_size) {
    asm volatile("cp.async.cg.shared.global [%0], [%1], 16, %2;\n"
                 :: "r"(dst), "l"(src), "r"(src_size));
}
__device__ __forceinline__ void mma_tf32(float* d, const uint4 a,
                                         uint32_t b0, uint32_t b1) {
    asm volatile(
        "mma.sync.aligned.m16n8k8.row.col.f32.tf32.tf32.f32 "
        "{%0,%1,%2,%3}, {%4,%5,%6,%7}, {%8,%9}, {%0,%1,%2,%3};\n"
        : "+f"(d[0]), "+f"(d[1]), "+f"(d[2]), "+f"(d[3])
        : "r"(a.x), "r"(a.y), "r"(a.z), "r"(a.w), "r"(b0), "r"(b1));
}

// ---- Prologue: weights f32 -> tf32, permuted to fragment order ----
__global__ __launch_bounds__(256)
void wfrag_kernel(const float* __restrict__ w) {
    const int idx  = blockIdx.x * 256 + threadIdx.x;
    const int lane = idx & 31;
    const int kk   = (idx >> 5) & 3;
    const int mt   = (idx >> 7) & 15;
    const int c    = (idx >> 11) & 7;
    const int s    = idx >> 14;
    const int g = lane >> 2, t = lane & 3;
    const int m = mt * 16 + g;
    const int k = c * 32 + kk * 8 + t;
    const float* ws = w + (size_t)s * CIN * CIN;
    uint4 r;
    r.x = f2tf32(ws[(size_t)m       * CIN + k]);
    r.y = f2tf32(ws[(size_t)(m + 8) * CIN + k]);
    r.z = f2tf32(ws[(size_t)m       * CIN + k + 4]);
    r.w = f2tf32(ws[(size_t)(m + 8) * CIN + k + 4]);
    *reinterpret_cast<uint4*>(g_wfrag + (size_t)idx * 4) = r;
}

// ---- Main GEMM ----
extern __shared__ uint32_t smem[];

__global__ __launch_bounds__(256, 2)
void subject_tf32_kernel(const float* __restrict__ x,
                         const float* __restrict__ bias,
                         const int* __restrict__ subj,
                         float* __restrict__ out)
{
    const int b  = blockIdx.z;
    const int m0 = blockIdx.y * TM;
    const int n0 = blockIdx.x * TN;

    const int s = subj[b];
    const float* __restrict__ X  = x    + (size_t)b * CIN * NSP;
    const float* __restrict__ Bv = bias + (size_t)s * CIN;
    float* __restrict__ O        = out  + (size_t)b * CIN * NSP;

    const size_t wbase = ((size_t)s * 8) * 16 + (m0 >> 4);

    const uint32_t sm_u32 = (uint32_t)__cvta_generic_to_shared(smem);

    const int tid    = threadIdx.x;
    const int wid    = tid >> 5;
    const int lane   = tid & 31;
    const int warp_m = wid & 3;
    const int warp_n = wid >> 2;
    const int group  = lane >> 2;
    const int tig    = lane & 3;
    const int bn     = warp_n * 64;

    float acc[2][8][4];
    #pragma unroll
    for (int mi = 0; mi < 2; mi++)
        #pragma unroll
        for (int ni = 0; ni < 8; ni++)
            #pragma unroll
            for (int r = 0; r < 4; r++)
                acc[mi][ni][r] = 0.0f;

    const int b_k  = tid >> 5;
    const int b_n4 = (tid & 31) << 2;
    const int gb_n = n0 + b_n4;
    const int b_ok = (gb_n < NSP);

    auto load_chunk = [&](int stage, int c) {
        const uint32_t sbase = sm_u32 + (uint32_t)(stage * STAGE_WORDS) * 4;
        // A: 16KB contiguous fragment block
        const uint32_t* srcA = g_wfrag + (wbase + (size_t)c * 16) * 512;
        #pragma unroll
        for (int j = 0; j < 4; j++) {
            int u = j * 256 + tid;
            cp16(sbase + (uint32_t)u * 16, srcA + (size_t)u * 4);
        }
        // B: [32][128] f32, coalesced rows
        const int k0 = c * TK;
        const uint32_t bbase = sbase + A_WORDS * 4;
        #pragma unroll
        for (int j = 0; j < 4; j++) {
            int k = b_k + j * 8;
            cp16z(bbase + (uint32_t)(k * BS_STRIDE + b_n4) * 4,
                  X + (size_t)(k0 + k) * NSP + (b_ok ? gb_n : 0),
                  b_ok ? 16 : 0);
        }
        asm volatile("cp.async.commit_group;\n");
    };

    auto compute_chunk = [&](int stage) {
        const uint32_t* A = smem + stage * STAGE_WORDS;
        const uint32_t* B = A + A_WORDS;
        uint32_t bw[2][16];
        auto load_bfrags = [&](uint32_t* d, int kk) {
            const int r0 = (kk * 8 + tig) * BS_STRIDE + bn + group;
            const int r1 = r0 + 4 * BS_STRIDE;
            #pragma unroll
            for (int ni = 0; ni < 8; ni++) {
                d[ni * 2]     = B[r0 + ni * 8];
                d[ni * 2 + 1] = B[r1 + ni * 8];
            }
        };
        load_bfrags(bw[0], 0);
        #pragma unroll
        for (int kk = 0; kk < 4; kk++) {
            if (kk < 3) load_bfrags(bw[(kk + 1) & 1], kk + 1);
            const uint32_t* bcur = bw[kk & 1];
            const int mtl = warp_m * 2;
            uint4 a0 = *reinterpret_cast<const uint4*>(
                &A[((mtl)     * 4 + kk) * 128 + lane * 4]);
            uint4 a1 = *reinterpret_cast<const uint4*>(
                &A[((mtl + 1) * 4 + kk) * 128 + lane * 4]);
            #pragma unroll
            for (int ni = 0; ni < 8; ni++) {
                mma_tf32(acc[0][ni], a0, bcur[ni * 2], bcur[ni * 2 + 1]);
                mma_tf32(acc[1][ni], a1, bcur[ni * 2], bcur[ni * 2 + 1]);
            }
        }
    };

    // Prologue: stage chunks 0 and 1.
    load_chunk(0, 0);
    load_chunk(1, 1);

    #pragma unroll 1
    for (int c = 0; c < NCHUNK; c++) {
        // Chunk c was committed 2 groups back (except the tail).
        if (c + 1 < NCHUNK) {
            asm volatile("cp.async.wait_group 1;\n");
        } else {
            asm volatile("cp.async.wait_group 0;\n");
        }
        __syncthreads();   // publish chunk c; buffer (c+2)%3's readers are done
        if (c + 2 < NCHUNK) load_chunk((c + 2) % NSTAGE, c + 2);
        compute_chunk(c % NSTAGE);
    }

    // Epilogue: bias add + float2 stores.
    const int am = warp_m * 32;
    #pragma unroll
    for (int mi = 0; mi < 2; mi++) {
        const int mrow = m0 + am + mi * 16 + group;
        const float bv0 = Bv[mrow];
        const float bv1 = Bv[mrow + 8];
        #pragma unroll
        for (int ni = 0; ni < 8; ni++) {
            const int n = n0 + bn + ni * 8 + tig * 2;
            if (n < NSP) {
                float2 v0 = make_float2(acc[mi][ni][0] + bv0, acc[mi][ni][1] + bv0);
                *reinterpret_cast<float2*>(&O[(size_t)mrow * NSP + n]) = v0;
                float2 v1 = make_float2(acc[mi][ni][2] + bv1, acc[mi][ni][3] + bv1);
                *reinterpret_cast<float2*>(&O[(size_t)(mrow + 8) * NSP + n]) = v1;
            }
        }
    }
}

extern "C" void kernel_launch(void* const* d_in, const int* in_sizes, int n_in,
                              void* d_out, int out_size) {
    const float* x      = (const float*)d_in[0];
    const float* weight = (const float*)d_in[1];
    const float* bias   = (const float*)d_in[2];
    const int*   subj   = (const int*)d_in[3];
    float*       out    = (float*)d_out;

    // 1) weights -> tf32 fragment-ordered scratch
    wfrag_kernel<<<NSUBJ * CIN * CIN / 4 / 256, 256>>>(weight);

    // 2) main GEMM
    cudaFuncSetAttribute(subject_tf32_kernel,
                         cudaFuncAttributeMaxDynamicSharedMemorySize, SMEM_BYTES);
    dim3 block(256);
    dim3 grid((NSP + TN - 1) / TN, CIN / TM, 256);   // (24, 2, 256)
    subject_tf32_kernel<<<grid, block, SMEM_BYTES>>>(x, bias, subj, out);
}

// round 12
// speedup vs baseline: 1.6246x; 1.1058x over previous
#include <cuda_runtime.h>
#include <cstdint>

// SubjectLayer: 256 SGEMMs (M=256,K=256,N=3000), tf32 mma.sync m16n8k8.
// R12: warp tile 64x64 (4 warps/CTA, CTA 128x128, 2 CTA/SM) to cut L1 operand
// bytes per HMMA 33% and break the tensor/L1 co-saturation seen in R8/R11.
// A: fragment-ordered tf32 scratch (LDS.128 frags). B: raw-f32 (tf32 HW trunc),
// row-major [k][n] smem, conflict-free LDS.32 frags, kk double-buffered.
// 3-stage cp.async ring (wait_group 1 = full-chunk latency cover).

#define NSP 3000
#define CIN 256
#define NSUBJ 128
#define TM 128
#define TN 128
#define TK 32
#define NCHUNK 8
#define NSTAGE 3

#define A_WORDS 4096                    // 128x32 tf32 fragment-ordered per stage
#define BS_STRIDE 136
#define B_WORDS (TK * BS_STRIDE)        // 4352
#define STAGE_WORDS (A_WORDS + B_WORDS) // 8448
#define SMEM_BYTES (NSTAGE * STAGE_WORDS * 4)   // 101376  (x2 CTA = 203KB <= 228KB)

// Fragment-ordered weights: [s][c(8)][mt(16)][kk(4)][lane(32)][r(4)]
__device__ uint32_t g_wfrag[NSUBJ * CIN * CIN];

__device__ __forceinline__ uint32_t f2tf32(float f) {
    uint32_t r;
    asm("cvt.rna.tf32.f32 %0, %1;" : "=r"(r) : "f"(f));
    return r;
}
__device__ __forceinline__ void cp16(uint32_t dst, const void* src) {
    asm volatile("cp.async.cg.shared.global [%0], [%1], 16;\n" :: "r"(dst), "l"(src));
}
__device__ __forceinline__ void cp16z(uint32_t dst, const void* src, int src_size) {
    asm volatile("cp.async.cg.shared.global [%0], [%1], 16, %2;\n"
                 :: "r"(dst), "l"(src), "r"(src_size));
}
__device__ __forceinline__ void mma_tf32(float* d, const uint4 a,
                                         uint32_t b0, uint32_t b1) {
    asm volatile(
        "mma.sync.aligned.m16n8k8.row.col.f32.tf32.tf32.f32 "
        "{%0,%1,%2,%3}, {%4,%5,%6,%7}, {%8,%9}, {%0,%1,%2,%3};\n"
        : "+f"(d[0]), "+f"(d[1]), "+f"(d[2]), "+f"(d[3])
        : "r"(a.x), "r"(a.y), "r"(a.z), "r"(a.w), "r"(b0), "r"(b1));
}

// ---- Prologue: weights f32 -> tf32, permuted to fragment order ----
__global__ __launch_bounds__(256)
void wfrag_kernel(const float* __restrict__ w) {
    const int idx  = blockIdx.x * 256 + threadIdx.x;
    const int lane = idx & 31;
    const int kk   = (idx >> 5) & 3;
    const int mt   = (idx >> 7) & 15;
    const int c    = (idx >> 11) & 7;
    const int s    = idx >> 14;
    const int g = lane >> 2, t = lane & 3;
    const int m = mt * 16 + g;
    const int k = c * 32 + kk * 8 + t;
    const float* ws = w + (size_t)s * CIN * CIN;
    uint4 r;
    r.x = f2tf32(ws[(size_t)m       * CIN + k]);
    r.y = f2tf32(ws[(size_t)(m + 8) * CIN + k]);
    r.z = f2tf32(ws[(size_t)m       * CIN + k + 4]);
    r.w = f2tf32(ws[(size_t)(m + 8) * CIN + k + 4]);
    *reinterpret_cast<uint4*>(g_wfrag + (size_t)idx * 4) = r;
}

// ---- Main GEMM ----
extern __shared__ uint32_t smem[];

__global__ __launch_bounds__(128, 2)
void subject_tf32_kernel(const float* __restrict__ x,
                         const float* __restrict__ bias,
                         const int* __restrict__ subj,
                         float* __restrict__ out)
{
    const int b  = blockIdx.z;
    const int m0 = blockIdx.y * TM;
    const int n0 = blockIdx.x * TN;

    const int s = subj[b];
    const float* __restrict__ X  = x    + (size_t)b * CIN * NSP;
    const float* __restrict__ Bv = bias + (size_t)s * CIN;
    float* __restrict__ O        = out  + (size_t)b * CIN * NSP;

    const size_t wbase = ((size_t)s * 8) * 16 + (m0 >> 4);

    const uint32_t sm_u32 = (uint32_t)__cvta_generic_to_shared(smem);

    const int tid    = threadIdx.x;
    const int wid    = tid >> 5;
    const int lane   = tid & 31;
    const int warp_m = wid & 1;        // 0..1 -> 64-row slabs
    const int warp_n = wid >> 1;       // 0..1 -> 64-col slabs
    const int group  = lane >> 2;      // 0..7
    const int tig    = lane & 3;       // 0..3
    const int bn     = warp_n * 64;
    const int mtl    = warp_m * 4;     // first m16 tile of this warp

    float acc[4][8][4];
    #pragma unroll
    for (int mi = 0; mi < 4; mi++)
        #pragma unroll
        for (int ni = 0; ni < 8; ni++)
            #pragma unroll
            for (int r = 0; r < 4; r++)
                acc[mi][ni][r] = 0.0f;

    // cp.async coords (128 threads).
    // A: 1024 uint4 per chunk -> 8 per thread.  B: 1024 uint4 -> 8 per thread.
    auto load_chunk = [&](int stage, int c) {
        const uint32_t sbase = sm_u32 + (uint32_t)(stage * STAGE_WORDS) * 4;
        const uint32_t* srcA = g_wfrag + (wbase + (size_t)c * 16) * 512;
        #pragma unroll
        for (int j = 0; j < 8; j++) {
            int u = j * 128 + tid;
            cp16(sbase + (uint32_t)u * 16, srcA + (size_t)u * 4);
        }
        const int k0 = c * TK;
        const uint32_t bbase = sbase + A_WORDS * 4;
        #pragma unroll
        for (int j = 0; j < 8; j++) {
            int u = j * 128 + tid;
            int k  = u >> 5;            // 0..31
            int n4 = (u & 31) << 2;     // 0..124
            int gn = n0 + n4;
            int ok = (gn < NSP);
            cp16z(bbase + (uint32_t)(k * BS_STRIDE + n4) * 4,
                  X + (size_t)(k0 + k) * NSP + (ok ? gn : 0),
                  ok ? 16 : 0);
        }
        asm volatile("cp.async.commit_group;\n");
    };

    auto compute_chunk = [&](int stage) {
        const uint32_t* A = smem + stage * STAGE_WORDS;
        const uint32_t* B = A + A_WORDS;
        uint32_t bw[2][16];
        auto load_bfrags = [&](uint32_t* d, int kk) {
            const int r0 = (kk * 8 + tig) * BS_STRIDE + bn + group;
            const int r1 = r0 + 4 * BS_STRIDE;
            #pragma unroll
            for (int ni = 0; ni < 8; ni++) {
                d[ni * 2]     = B[r0 + ni * 8];
                d[ni * 2 + 1] = B[r1 + ni * 8];
            }
        };
        load_bfrags(bw[0], 0);
        #pragma unroll
        for (int kk = 0; kk < 4; kk++) {
            if (kk < 3) load_bfrags(bw[(kk + 1) & 1], kk + 1);
            const uint32_t* bcur = bw[kk & 1];
            uint4 a[4];
            #pragma unroll
            for (int mi = 0; mi < 4; mi++)
                a[mi] = *reinterpret_cast<const uint4*>(
                    &A[((mtl + mi) * 4 + kk) * 128 + lane * 4]);
            #pragma unroll
            for (int ni = 0; ni < 8; ni++) {
                #pragma unroll
                for (int mi = 0; mi < 4; mi++)
                    mma_tf32(acc[mi][ni], a[mi], bcur[ni * 2], bcur[ni * 2 + 1]);
            }
        }
    };

    // Prologue: stage chunks 0 and 1.
    load_chunk(0, 0);
    load_chunk(1, 1);

    #pragma unroll 1
    for (int c = 0; c < NCHUNK; c++) {
        if (c + 1 < NCHUNK) {
            asm volatile("cp.async.wait_group 1;\n");
        } else {
            asm volatile("cp.async.wait_group 0;\n");
        }
        __syncthreads();
        if (c + 2 < NCHUNK) load_chunk((c + 2) % NSTAGE, c + 2);
        compute_chunk(c % NSTAGE);
    }

    // Epilogue: bias add + float2 stores.
    const int am = warp_m * 64;
    #pragma unroll
    for (int mi = 0; mi < 4; mi++) {
        const int mrow = m0 + am + mi * 16 + group;
        const float bv0 = Bv[mrow];
        const float bv1 = Bv[mrow + 8];
        #pragma unroll
        for (int ni = 0; ni < 8; ni++) {
            const int n = n0 + bn + ni * 8 + tig * 2;
            if (n < NSP) {
                float2 v0 = make_float2(acc[mi][ni][0] + bv0, acc[mi][ni][1] + bv0);
                *reinterpret_cast<float2*>(&O[(size_t)mrow * NSP + n]) = v0;
                float2 v1 = make_float2(acc[mi][ni][2] + bv1, acc[mi][ni][3] + bv1);
                *reinterpret_cast<float2*>(&O[(size_t)(mrow + 8) * NSP + n]) = v1;
            }
        }
    }
}

extern "C" void kernel_launch(void* const* d_in, const int* in_sizes, int n_in,
                              void* d_out, int out_size) {
    const float* x      = (const float*)d_in[0];
    const float* weight = (const float*)d_in[1];
    const float* bias   = (const float*)d_in[2];
    const int*   subj   = (const int*)d_in[3];
    float*       out    = (float*)d_out;

    // 1) weights -> tf32 fragment-ordered scratch
    wfrag_kernel<<<NSUBJ * CIN * CIN / 4 / 256, 256>>>(weight);

    // 2) main GEMM
    cudaFuncSetAttribute(subject_tf32_kernel,
                         cudaFuncAttributeMaxDynamicSharedMemorySize, SMEM_BYTES);
    dim3 block(128);
    dim3 grid((NSP + TN - 1) / TN, CIN / TM, 256);   // (24, 2, 256)
    subject_tf32_kernel<<<grid, block, SMEM_BYTES>>>(x, bias, subj, out);
}

// round 15
// speedup vs baseline: 1.9116x; 1.1767x over previous
#include <cuda_runtime.h>
#include <cstdint>

// SubjectLayer: 256 SGEMMs (M=256,K=256,N=3000) via fp16 mma.sync m16n8k16.
// R13 = R12 topology (CTA 128x128, 4 warps 64x64, ring-3 cp.async, 2 CTA/SM)
// with fp16 tensor path: weights pre-packed to f16x2 fragment order (halved A
// bytes), X loaded f32 and packed to f16x2 in registers (cvt.rn.f16x2.f32).
// fp16 mantissa (10b) == tf32 mantissa -> comparable error, 2x MACs/instr.

#define NSP 3000
#define CIN 256
#define NSUBJ 128
#define TM 128
#define TN 128
#define TK 32
#define NCHUNK 8
#define NSTAGE 3

#define A_WORDS 2048                    // 128x32 fp16 fragment-ordered per stage
#define BF_STRIDE 132                   // f32 B row stride (128+4): 2t-row frags conflict-free
#define B_WORDS (TK * BF_STRIDE)        // 4224
#define STAGE_WORDS (A_WORDS + B_WORDS) // 6272
#define SMEM_BYTES (NSTAGE * STAGE_WORDS * 4)   // 75264  (x2 CTA = 150KB <= 228KB)

// fp16 fragment-ordered weights: [s][c(8)][mt(16)][step(2)][lane(32)][reg(4)]
//   reg0={W[m][k0],W[m][k0+1]} reg1={W[m+8][k0],...} reg2={W[m][k0+8],..} reg3={W[m+8][k0+8],..}
//   m=mt*16+g, k0=c*32+step*16+2t
__device__ uint32_t g_wfrag[4 * 1024 * 1024];   // 16.8MB

__device__ __forceinline__ uint32_t packh(float lo, float hi) {
    uint32_t d;
    asm("cvt.rn.f16x2.f32 %0, %1, %2;" : "=r"(d) : "f"(hi), "f"(lo));
    return d;
}
__device__ __forceinline__ void cp16(uint32_t dst, const void* src) {
    asm volatile("cp.async.cg.shared.global [%0], [%1], 16;\n" :: "r"(dst), "l"(src));
}
__device__ __forceinline__ void cp16z(uint32_t dst, const void* src, int src_size) {
    asm volatile("cp.async.cg.shared.global [%0], [%1], 16, %2;\n"
                 :: "r"(dst), "l"(src), "r"(src_size));
}
__device__ __forceinline__ void mma_f16(float* d, const uint4 a,
                                        uint32_t b0, uint32_t b1) {
    asm volatile(
        "mma.sync.aligned.m16n8k16.row.col.f32.f16.f16.f32 "
        "{%0,%1,%2,%3}, {%4,%5,%6,%7}, {%8,%9}, {%0,%1,%2,%3};\n"
        : "+f"(d[0]), "+f"(d[1]), "+f"(d[2]), "+f"(d[3])
        : "r"(a.x), "r"(a.y), "r"(a.z), "r"(a.w), "r"(b0), "r"(b1));
}

// ---- Prologue: weights f32 -> fp16-packed fragment order ----
__global__ __launch_bounds__(256)
void wfrag_kernel(const float* __restrict__ w) {
    const int idx  = blockIdx.x * 256 + threadIdx.x;   // one uint4 per thread
    const int lane = idx & 31;
    const int step = (idx >> 5) & 1;
    const int mt   = (idx >> 6) & 15;
    const int c    = (idx >> 10) & 7;
    const int s    = idx >> 13;
    const int g = lane >> 2, t = lane & 3;
    const int m  = mt * 16 + g;
    const int k0 = c * 32 + step * 16 + 2 * t;
    const float* ws = w + (size_t)s * CIN * CIN;
    const float* r0 = ws + (size_t)m * CIN + k0;
    const float* r1 = ws + (size_t)(m + 8) * CIN + k0;
    uint4 r;
    r.x = packh(r0[0], r0[1]);
    r.y = packh(r1[0], r1[1]);
    r.z = packh(r0[8], r0[9]);
    r.w = packh(r1[8], r1[9]);
    reinterpret_cast<uint4*>(g_wfrag)[idx] = r;
}

// ---- Main GEMM ----
extern __shared__ uint32_t smem[];

__global__ __launch_bounds__(128, 2)
void subject_f16_kernel(const float* __restrict__ x,
                        const float* __restrict__ bias,
                        const int* __restrict__ subj,
                        float* __restrict__ out)
{
    const int b  = blockIdx.z;
    const int m0 = blockIdx.y * TM;
    const int n0 = blockIdx.x * TN;

    const int s = subj[b];
    const float* __restrict__ X  = x    + (size_t)b * CIN * NSP;
    const float* __restrict__ Bv = bias + (size_t)s * CIN;
    float* __restrict__ O        = out  + (size_t)b * CIN * NSP;

    // A chunk block (8 local mt x 256 words): (wbase + c*16)*256
    const size_t wbase = (size_t)s * 128 + (m0 >> 4);

    const uint32_t sm_u32 = (uint32_t)__cvta_generic_to_shared(smem);

    const int tid    = threadIdx.x;
    const int wid    = tid >> 5;
    const int lane   = tid & 31;
    const int warp_m = wid & 1;
    const int warp_n = wid >> 1;
    const int group  = lane >> 2;
    const int tig    = lane & 3;
    const int bn     = warp_n * 64;
    const int mtl    = warp_m * 4;     // local mt base (0 or 4)

    float acc[4][8][4];
    #pragma unroll
    for (int mi = 0; mi < 4; mi++)
        #pragma unroll
        for (int ni = 0; ni < 8; ni++)
            #pragma unroll
            for (int r = 0; r < 4; r++)
                acc[mi][ni][r] = 0.0f;

    auto load_chunk = [&](int stage, int c) {
        const uint32_t sbase = sm_u32 + (uint32_t)(stage * STAGE_WORDS) * 4;
        // A: 8KB contiguous fp16 fragment block (512 uint4)
        const uint32_t* srcA = g_wfrag + (wbase + (size_t)c * 16) * 256;
        #pragma unroll
        for (int j = 0; j < 4; j++) {
            int u = j * 128 + tid;
            cp16(sbase + (uint32_t)u * 16, srcA + (size_t)u * 4);
        }
        // B: [32][128] f32 rows (stride 132), coalesced
        const int k0 = c * TK;
        const uint32_t bbase = sbase + A_WORDS * 4;
        #pragma unroll
        for (int j = 0; j < 8; j++) {
            int u = j * 128 + tid;
            int k  = u >> 5;
            int n4 = (u & 31) << 2;
            int gn = n0 + n4;
            int ok = (gn < NSP);
            cp16z(bbase + (uint32_t)(k * BF_STRIDE + n4) * 4,
                  X + (size_t)(k0 + k) * NSP + (ok ? gn : 0),
                  ok ? 16 : 0);
        }
        asm volatile("cp.async.commit_group;\n");
    };

    auto compute_chunk = [&](int stage) {
        const uint32_t* A = smem + stage * STAGE_WORDS;
        const float* Bf = reinterpret_cast<const float*>(A + A_WORDS);
        uint32_t bw[2][16];
        auto load_bfrags = [&](uint32_t* d, int step) {
            const int r0 = (step * 16 + 2 * tig) * BF_STRIDE + bn + group;
            #pragma unroll
            for (int ni = 0; ni < 8; ni++) {
                float f0 = Bf[r0 + ni * 8];                     // k = 2t
                float f1 = Bf[r0 + BF_STRIDE + ni * 8];         // k = 2t+1
                float f2 = Bf[r0 + 8 * BF_STRIDE + ni * 8];     // k = 2t+8
                float f3 = Bf[r0 + 9 * BF_STRIDE + ni * 8];     // k = 2t+9
                d[ni * 2]     = packh(f0, f1);
                d[ni * 2 + 1] = packh(f2, f3);
            }
        };
        load_bfrags(bw[0], 0);
        #pragma unroll
        for (int step = 0; step < 2; step++) {
            if (step == 0) load_bfrags(bw[1], 1);
            const uint32_t* bcur = bw[step];
            uint4 a[4];
            #pragma unroll
            for (int mi = 0; mi < 4; mi++)
                a[mi] = *reinterpret_cast<const uint4*>(
                    &A[(uint32_t)(((mtl + mi) * 2 + step) * 128 + lane * 4)]);
            #pragma unroll
            for (int ni = 0; ni < 8; ni++) {
                #pragma unroll
                for (int mi = 0; mi < 4; mi++)
                    mma_f16(acc[mi][ni], a[mi], bcur[ni * 2], bcur[ni * 2 + 1]);
            }
        }
    };

    // Prologue: stage chunks 0 and 1.
    load_chunk(0, 0);
    load_chunk(1, 1);

    #pragma unroll 1
    for (int c = 0; c < NCHUNK; c++) {
        if (c + 1 < NCHUNK) {
            asm volatile("cp.async.wait_group 1;\n");
        } else {
            asm volatile("cp.async.wait_group 0;\n");
        }
        __syncthreads();
        if (c + 2 < NCHUNK) load_chunk((c + 2) % NSTAGE, c + 2);
        compute_chunk(c % NSTAGE);
    }

    // Epilogue: bias add + float2 stores.
    const int am = warp_m * 64;
    #pragma unroll
    for (int mi = 0; mi < 4; mi++) {
        const int mrow = m0 + am + mi * 16 + group;
        const float bv0 = Bv[mrow];
        const float bv1 = Bv[mrow + 8];
        #pragma unroll
        for (int ni = 0; ni < 8; ni++) {
            const int n = n0 + bn + ni * 8 + tig * 2;
            if (n < NSP) {
                float2 v0 = make_float2(acc[mi][ni][0] + bv0, acc[mi][ni][1] + bv0);
                *reinterpret_cast<float2*>(&O[(size_t)mrow * NSP + n]) = v0;
                float2 v1 = make_float2(acc[mi][ni][2] + bv1, acc[mi][ni][3] + bv1);
                *reinterpret_cast<float2*>(&O[(size_t)(mrow + 8) * NSP + n]) = v1;
            }
        }
    }
}

extern "C" void kernel_launch(void* const* d_in, const int* in_sizes, int n_in,
                              void* d_out, int out_size) {
    const float* x      = (const float*)d_in[0];
    const float* weight = (const float*)d_in[1];
    const float* bias   = (const float*)d_in[2];
    const int*   subj   = (const int*)d_in[3];
    float*       out    = (float*)d_out;

    // 1) weights -> fp16-packed fragment-ordered scratch (1M uint4)
    wfrag_kernel<<<4096, 256>>>(weight);

    // 2) main GEMM
    cudaFuncSetAttribute(subject_f16_kernel,
                         cudaFuncAttributeMaxDynamicSharedMemorySize, SMEM_BYTES);
    dim3 block(128);
    dim3 grid((NSP + TN - 1) / TN, CIN / TM, 256);   // (24, 2, 256)
    subject_f16_kernel<<<grid, block, SMEM_BYTES>>>(x, bias, subj, out);
}